// round 3
// baseline (speedup 1.0000x reference)
#include <cuda_runtime.h>
#include <cuda_bf16.h>

// ---------------------------------------------------------------------------
// GIN layer: out = relu( relu( (x + scatter_sum(x[src] -> dst)) @ W1^T + b1 ) @ W2^T + b2 )
// N = 100000, D = 128, E = 625000.
//
// R3: replace float-atomic scatter with CSR build (counting sort by dst)
//     + deterministic warp-per-node gather-aggregate.
//   K1: cnt = 0
//   K2: cnt[dst[e]]++                        (int atomics, spread)
//   K3: off = exscan(cnt); cur = off         (single-block slice scan)
//   K4: nbr[cur[dst[e]]++] = src[e]          (int atomics)
//   K5: agg[i] = x[i] + sum_{s in nbr(i)} x[s]   (warp/node, registers)
//   K6: fused tf32 MLP on agg
// ---------------------------------------------------------------------------

#define D 128
#define MAX_N 100000
#define MAX_E 625000
#define SA 132
#define SB 136

__device__ float g_agg[(size_t)MAX_N * D];
__device__ int   g_off[MAX_N + 1];
__device__ int   g_cur[MAX_N];       // counts, then cursors
__device__ int   g_nbr[MAX_E];

// ---------------------------------------------------------------------------
__global__ void zero_cnt_kernel(int n) {
    int i = blockIdx.x * blockDim.x + threadIdx.x;
    if (i < n) g_cur[i] = 0;
}

__global__ void hist_kernel(const int* __restrict__ dst, int E) {
    int e = blockIdx.x * blockDim.x + threadIdx.x;
    if (e < E) atomicAdd(&g_cur[dst[e]], 1);
}

// Single-block slice scan: 1024 threads, each owns a contiguous slice.
__global__ void scan_kernel(int n) {
    __shared__ int ssum[1024];
    const int tid = threadIdx.x;
    const int per = (n + 1023) / 1024;
    const int s   = tid * per;
    const int e   = min(s + per, n);

    int sum = 0;
    for (int i = s; i < e; ++i) sum += g_cur[i];
    ssum[tid] = sum;
    __syncthreads();

    // Hillis-Steele inclusive scan over 1024 partials.
    for (int off = 1; off < 1024; off <<= 1) {
        int t = (tid >= off) ? ssum[tid - off] : 0;
        __syncthreads();
        ssum[tid] += t;
        __syncthreads();
    }
    int run = ssum[tid] - sum;   // exclusive prefix of this slice

    for (int i = s; i < e; ++i) {
        int c = g_cur[i];
        g_off[i] = run;
        g_cur[i] = run;          // cursor init
        run += c;
    }
    if (tid == 1023) g_off[n] = run;
}

__global__ void bucket_kernel(const int* __restrict__ src,
                              const int* __restrict__ dst, int E) {
    int e = blockIdx.x * blockDim.x + threadIdx.x;
    if (e < E) {
        int pos = atomicAdd(&g_cur[dst[e]], 1);
        g_nbr[pos] = src[e];
    }
}

// ---------------------------------------------------------------------------
// One warp per node: acc = x[i] + sum over neighbors, all in registers.
__global__ void agg_kernel(const float* __restrict__ x, int n) {
    int wid  = (int)(((long)blockIdx.x * blockDim.x + threadIdx.x) >> 5);
    int lane = threadIdx.x & 31;
    if (wid >= n) return;

    const int beg = g_off[wid];
    const int end = g_off[wid + 1];

    float4 acc = *(const float4*)(x + (long)wid * D + lane * 4);

    int t = beg;
    for (; t + 3 < end; t += 4) {
        int s0 = g_nbr[t], s1 = g_nbr[t + 1], s2 = g_nbr[t + 2], s3 = g_nbr[t + 3];
        float4 v0 = *(const float4*)(x + (long)s0 * D + lane * 4);
        float4 v1 = *(const float4*)(x + (long)s1 * D + lane * 4);
        float4 v2 = *(const float4*)(x + (long)s2 * D + lane * 4);
        float4 v3 = *(const float4*)(x + (long)s3 * D + lane * 4);
        acc.x += v0.x + v1.x + v2.x + v3.x;
        acc.y += v0.y + v1.y + v2.y + v3.y;
        acc.z += v0.z + v1.z + v2.z + v3.z;
        acc.w += v0.w + v1.w + v2.w + v3.w;
    }
    for (; t < end; ++t) {
        int s0 = g_nbr[t];
        float4 v0 = *(const float4*)(x + (long)s0 * D + lane * 4);
        acc.x += v0.x; acc.y += v0.y; acc.z += v0.z; acc.w += v0.w;
    }
    *(float4*)(g_agg + (long)wid * D + lane * 4) = acc;
}

// ---------------------------------------------------------------------------
__device__ __forceinline__ unsigned f2tf32(float f) {
    unsigned r;
    asm("cvt.rna.tf32.f32 %0, %1;" : "=r"(r) : "f"(f));
    return r;
}

__device__ __forceinline__ void mma_tf32(float c[4], const unsigned a[4],
                                         const unsigned b[2]) {
    asm volatile(
        "mma.sync.aligned.m16n8k8.row.col.f32.tf32.tf32.f32 "
        "{%0,%1,%2,%3}, {%4,%5,%6,%7}, {%8,%9}, {%0,%1,%2,%3};"
        : "+f"(c[0]), "+f"(c[1]), "+f"(c[2]), "+f"(c[3])
        : "r"(a[0]), "r"(a[1]), "r"(a[2]), "r"(a[3]), "r"(b[0]), "r"(b[1]));
}

// Block: 256 threads (8 warps) -> 128x128 tile; warp tile 32x64.
__global__ __launch_bounds__(256, 1)
void mlp_kernel(const float* __restrict__ W1, const float* __restrict__ b1,
                const float* __restrict__ W2, const float* __restrict__ b2,
                float* __restrict__ out, int n) {
    extern __shared__ float sm[];
    float* Abuf = sm;                     // 128*SA
    float* W1t  = sm + 128 * SA;          // 128*SB
    float* W2t  = W1t + 128 * SB;         // 128*SB

    const int tid  = threadIdx.x;
    const int w    = tid >> 5;
    const int lane = tid & 31;
    const int lr   = lane >> 2;
    const int lc   = lane & 3;
    const int rw   = (w & 3) * 32;
    const int cw   = (w >> 2) * 64;
    const int row0 = blockIdx.x * 128;

    for (int idx = tid; idx < D * D; idx += 256) {
        int nn = idx >> 7;
        int m  = idx & 127;
        W1t[m * SB + nn] = __uint_as_float(f2tf32(W1[idx]));
        W2t[m * SB + nn] = __uint_as_float(f2tf32(W2[idx]));
    }

    {
        int i  = tid >> 5;
        int k4 = tid & 31;
        for (int ii = i; ii < 128; ii += 8) {
            int row = row0 + ii;
            float4 v = make_float4(0.f, 0.f, 0.f, 0.f);
            if (row < n) v = *(const float4*)(g_agg + (long)row * D + k4 * 4);
            uint4 t;
            t.x = f2tf32(v.x); t.y = f2tf32(v.y);
            t.z = f2tf32(v.z); t.w = f2tf32(v.w);
            *(uint4*)(Abuf + ii * SA + k4 * 4) = t;
        }
    }
    __syncthreads();

    float acc[2][8][4];
#pragma unroll
    for (int mt = 0; mt < 2; ++mt)
#pragma unroll
        for (int nt = 0; nt < 8; ++nt)
#pragma unroll
            for (int q = 0; q < 4; ++q) acc[mt][nt][q] = 0.f;

    // ---- GEMM 1 ----
#pragma unroll 4
    for (int ks = 0; ks < 16; ++ks) {
        const int k0 = ks * 8;
        unsigned a[2][4];
#pragma unroll
        for (int mt = 0; mt < 2; ++mt) {
            const float* p = Abuf + (rw + 16 * mt + lr) * SA + k0 + lc;
            a[mt][0] = __float_as_uint(p[0]);
            a[mt][1] = __float_as_uint(p[8 * SA]);
            a[mt][2] = __float_as_uint(p[4]);
            a[mt][3] = __float_as_uint(p[8 * SA + 4]);
        }
        unsigned b[8][2];
#pragma unroll
        for (int nt = 0; nt < 8; ++nt) {
            const float* p = W1t + (k0 + lc) * SB + cw + 8 * nt + lr;
            b[nt][0] = __float_as_uint(p[0]);
            b[nt][1] = __float_as_uint(p[4 * SB]);
        }
#pragma unroll
        for (int mt = 0; mt < 2; ++mt)
#pragma unroll
            for (int nt = 0; nt < 8; ++nt) mma_tf32(acc[mt][nt], a[mt], b[nt]);
    }
    __syncthreads();

    // Epilogue 1: bias + relu -> h1 (tf32) in Abuf.
#pragma unroll
    for (int mt = 0; mt < 2; ++mt) {
#pragma unroll
        for (int nt = 0; nt < 8; ++nt) {
            int col = cw + 8 * nt + 2 * lc;
            int r_a = rw + 16 * mt + lr;
            float bc0 = b1[col], bc1 = b1[col + 1];
            uint2 u0, u1;
            u0.x = f2tf32(fmaxf(acc[mt][nt][0] + bc0, 0.f));
            u0.y = f2tf32(fmaxf(acc[mt][nt][1] + bc1, 0.f));
            u1.x = f2tf32(fmaxf(acc[mt][nt][2] + bc0, 0.f));
            u1.y = f2tf32(fmaxf(acc[mt][nt][3] + bc1, 0.f));
            *(uint2*)(Abuf + r_a * SA + col)       = u0;
            *(uint2*)(Abuf + (r_a + 8) * SA + col) = u1;
            acc[mt][nt][0] = acc[mt][nt][1] = 0.f;
            acc[mt][nt][2] = acc[mt][nt][3] = 0.f;
        }
    }
    __syncthreads();

    // ---- GEMM 2 ----
#pragma unroll 4
    for (int ks = 0; ks < 16; ++ks) {
        const int k0 = ks * 8;
        unsigned a[2][4];
#pragma unroll
        for (int mt = 0; mt < 2; ++mt) {
            const float* p = Abuf + (rw + 16 * mt + lr) * SA + k0 + lc;
            a[mt][0] = __float_as_uint(p[0]);
            a[mt][1] = __float_as_uint(p[8 * SA]);
            a[mt][2] = __float_as_uint(p[4]);
            a[mt][3] = __float_as_uint(p[8 * SA + 4]);
        }
        unsigned b[8][2];
#pragma unroll
        for (int nt = 0; nt < 8; ++nt) {
            const float* p = W2t + (k0 + lc) * SB + cw + 8 * nt + lr;
            b[nt][0] = __float_as_uint(p[0]);
            b[nt][1] = __float_as_uint(p[4 * SB]);
        }
#pragma unroll
        for (int mt = 0; mt < 2; ++mt)
#pragma unroll
            for (int nt = 0; nt < 8; ++nt) mma_tf32(acc[mt][nt], a[mt], b[nt]);
    }

    // Epilogue 2: bias + relu -> global.
#pragma unroll
    for (int mt = 0; mt < 2; ++mt) {
#pragma unroll
        for (int nt = 0; nt < 8; ++nt) {
            int col = cw + 8 * nt + 2 * lc;
            int r_a = rw + 16 * mt + lr;
            float bc0 = b2[col], bc1 = b2[col + 1];
            int row = row0 + r_a;
            if (row < n) {
                float2 v;
                v.x = fmaxf(acc[mt][nt][0] + bc0, 0.f);
                v.y = fmaxf(acc[mt][nt][1] + bc1, 0.f);
                *(float2*)(out + (long)row * D + col) = v;
            }
            if (row + 8 < n) {
                float2 v;
                v.x = fmaxf(acc[mt][nt][2] + bc0, 0.f);
                v.y = fmaxf(acc[mt][nt][3] + bc1, 0.f);
                *(float2*)(out + (long)(row + 8) * D + col) = v;
            }
        }
    }
}

// ---------------------------------------------------------------------------
extern "C" void kernel_launch(void* const* d_in, const int* in_sizes, int n_in,
                              void* d_out, int out_size) {
    const float* x  = (const float*)d_in[0];
    const int*   ei = (const int*)d_in[1];
    const float* W1 = (const float*)d_in[2];
    const float* b1 = (const float*)d_in[3];
    const float* W2 = (const float*)d_in[4];
    const float* b2 = (const float*)d_in[5];
    float* out = (float*)d_out;

    const int n = in_sizes[0] / D;
    const int E = in_sizes[1] / 2;
    const int* src = ei;
    const int* dst = ei + E;

    zero_cnt_kernel<<<(n + 255) / 256, 256>>>(n);
    hist_kernel<<<(E + 255) / 256, 256>>>(dst, E);
    scan_kernel<<<1, 1024>>>(n);
    bucket_kernel<<<(E + 255) / 256, 256>>>(src, dst, E);

    {
        long threads = (long)n * 32;
        int blocks = (int)((threads + 255) / 256);
        agg_kernel<<<blocks, 256>>>(x, n);
    }

    {
        int smem = (128 * SA + 2 * 128 * SB) * (int)sizeof(float);
        cudaFuncSetAttribute(mlp_kernel,
                             cudaFuncAttributeMaxDynamicSharedMemorySize, smem);
        int blocks = (n + 127) / 128;
        mlp_kernel<<<blocks, 256, smem>>>(W1, b1, W2, b2, out, n);
    }
}

// round 8
// speedup vs baseline: 1.4999x; 1.4999x over previous
#include <cuda_runtime.h>
#include <cuda_bf16.h>

// ---------------------------------------------------------------------------
// GIN layer: out = relu( relu( (x + scatter_sum(x[src] -> dst)) @ W1^T + b1 ) @ W2^T + b2 )
// N = 100000, D = 128, E = 625000.
//
//   K1: agg = 0                        (zero-fill; x folded into MLP input)
//   K2: agg[dst] += x[src]             (1 warp/edge, red.global.add.v4.f32)
//   K3: fused MLP with tf32 mma.sync   (A = x + agg; h1 in smem; 2 GEMMs fused)
// ---------------------------------------------------------------------------

#define D 128
#define MAX_N 100000
#define SA 132   // Abuf row stride (floats): bank = 4*row'+k' -> conflict-free frags
#define SB 136   // W row stride   (floats): bank = 8*k'+n'   -> conflict-free frags

__device__ float g_agg[(size_t)MAX_N * D];

// ---------------------------------------------------------------------------
__global__ void zero_agg_kernel(int total4) {
    int i = blockIdx.x * blockDim.x + threadIdx.x;
    if (i < total4) ((float4*)g_agg)[i] = make_float4(0.f, 0.f, 0.f, 0.f);
}

// ---------------------------------------------------------------------------
__global__ void scatter_kernel(const float* __restrict__ x,
                               const int* __restrict__ src,
                               const int* __restrict__ dst,
                               int E) {
    long tid = (long)blockIdx.x * blockDim.x + threadIdx.x;
    int e    = (int)(tid >> 5);
    int lane = (int)(tid & 31);
    if (e >= E) return;
    int s = src[e];
    int d = dst[e];
    const float4 v = *(const float4*)(x + (long)s * D + lane * 4);
    float* p = g_agg + (long)d * D + lane * 4;
    asm volatile("red.global.add.v4.f32 [%0], {%1, %2, %3, %4};"
                 :: "l"(p), "f"(v.x), "f"(v.y), "f"(v.z), "f"(v.w)
                 : "memory");
}

// ---------------------------------------------------------------------------
__device__ __forceinline__ unsigned f2tf32(float f) {
    unsigned r;
    asm("cvt.rna.tf32.f32 %0, %1;" : "=r"(r) : "f"(f));
    return r;
}

__device__ __forceinline__ void mma_tf32(float c[4], const unsigned a[4],
                                         const unsigned b[2]) {
    asm volatile(
        "mma.sync.aligned.m16n8k8.row.col.f32.tf32.tf32.f32 "
        "{%0,%1,%2,%3}, {%4,%5,%6,%7}, {%8,%9}, {%0,%1,%2,%3};"
        : "+f"(c[0]), "+f"(c[1]), "+f"(c[2]), "+f"(c[3])
        : "r"(a[0]), "r"(a[1]), "r"(a[2]), "r"(a[3]), "r"(b[0]), "r"(b[1]));
}

// ---------------------------------------------------------------------------
// Block: 256 threads (8 warps) -> 128 rows x 128 cols tile.
// Warp tile: 32 rows x 64 cols (2 m-tiles x 8 n-tiles of m16n8k8).
// smem: Abuf[128][SA] (A tile / h1 tile, tf32 bits), W1t/W2t[128][SB] (W^T, tf32).
__global__ __launch_bounds__(256, 1)
void mlp_kernel(const float* __restrict__ x,
                const float* __restrict__ W1, const float* __restrict__ b1,
                const float* __restrict__ W2, const float* __restrict__ b2,
                float* __restrict__ out, int n) {
    extern __shared__ float sm[];
    float* Abuf = sm;                     // 128*SA
    float* W1t  = sm + 128 * SA;          // 128*SB
    float* W2t  = W1t + 128 * SB;         // 128*SB

    const int tid  = threadIdx.x;
    const int w    = tid >> 5;
    const int lane = tid & 31;
    const int lr   = lane >> 2;   // 0..7  (groupID)
    const int lc   = lane & 3;    // 0..3  (threadID_in_group)
    const int rw   = (w & 3) * 32;    // warp row offset in tile
    const int cw   = (w >> 2) * 64;   // warp col offset in tile
    const int row0 = blockIdx.x * 128;

    // Load W1^T, W2^T into smem as tf32. Wt[m][nn] = W[nn][m].
    for (int idx = tid; idx < D * D; idx += 256) {
        int nn = idx >> 7;        // output feature (row of W)
        int m  = idx & 127;       // input feature  (col of W)
        W1t[m * SB + nn] = __uint_as_float(f2tf32(W1[idx]));
        W2t[m * SB + nn] = __uint_as_float(f2tf32(W2[idx]));
    }

    // Load A tile: A = x + agg, converted to tf32.
    {
        int i  = tid >> 5;              // 0..7 (row group start)
        int k4 = tid & 31;              // 0..31 (float4 index)
        for (int ii = i; ii < 128; ii += 8) {
            int row = row0 + ii;
            float4 v = make_float4(0.f, 0.f, 0.f, 0.f);
            if (row < n) {
                float4 vx = *(const float4*)(x + (long)row * D + k4 * 4);
                float4 vg = *(const float4*)(g_agg + (long)row * D + k4 * 4);
                v.x = vx.x + vg.x; v.y = vx.y + vg.y;
                v.z = vx.z + vg.z; v.w = vx.w + vg.w;
            }
            uint4 t;
            t.x = f2tf32(v.x); t.y = f2tf32(v.y);
            t.z = f2tf32(v.z); t.w = f2tf32(v.w);
            *(uint4*)(Abuf + ii * SA + k4 * 4) = t;
        }
    }
    __syncthreads();

    float acc[2][8][4];
#pragma unroll
    for (int mt = 0; mt < 2; ++mt)
#pragma unroll
        for (int nt = 0; nt < 8; ++nt)
#pragma unroll
            for (int q = 0; q < 4; ++q) acc[mt][nt][q] = 0.f;

    // ---- GEMM 1: acc = A @ W1^T ----
#pragma unroll 4
    for (int ks = 0; ks < 16; ++ks) {
        const int k0 = ks * 8;
        unsigned a[2][4];
#pragma unroll
        for (int mt = 0; mt < 2; ++mt) {
            const float* p = Abuf + (rw + 16 * mt + lr) * SA + k0 + lc;
            a[mt][0] = __float_as_uint(p[0]);
            a[mt][1] = __float_as_uint(p[8 * SA]);
            a[mt][2] = __float_as_uint(p[4]);
            a[mt][3] = __float_as_uint(p[8 * SA + 4]);
        }
        unsigned b[8][2];
#pragma unroll
        for (int nt = 0; nt < 8; ++nt) {
            const float* p = W1t + (k0 + lc) * SB + cw + 8 * nt + lr;
            b[nt][0] = __float_as_uint(p[0]);
            b[nt][1] = __float_as_uint(p[4 * SB]);
        }
#pragma unroll
        for (int mt = 0; mt < 2; ++mt)
#pragma unroll
            for (int nt = 0; nt < 8; ++nt) mma_tf32(acc[mt][nt], a[mt], b[nt]);
    }
    __syncthreads();   // everyone done reading Abuf

    // Epilogue 1: bias + relu -> h1 (tf32) back into Abuf.
#pragma unroll
    for (int mt = 0; mt < 2; ++mt) {
#pragma unroll
        for (int nt = 0; nt < 8; ++nt) {
            int col = cw + 8 * nt + 2 * lc;
            int r_a = rw + 16 * mt + lr;
            float bc0 = b1[col], bc1 = b1[col + 1];
            uint2 u0, u1;
            u0.x = f2tf32(fmaxf(acc[mt][nt][0] + bc0, 0.f));
            u0.y = f2tf32(fmaxf(acc[mt][nt][1] + bc1, 0.f));
            u1.x = f2tf32(fmaxf(acc[mt][nt][2] + bc0, 0.f));
            u1.y = f2tf32(fmaxf(acc[mt][nt][3] + bc1, 0.f));
            *(uint2*)(Abuf + r_a * SA + col)       = u0;
            *(uint2*)(Abuf + (r_a + 8) * SA + col) = u1;
            acc[mt][nt][0] = acc[mt][nt][1] = 0.f;
            acc[mt][nt][2] = acc[mt][nt][3] = 0.f;
        }
    }
    __syncthreads();

    // ---- GEMM 2: acc = h1 @ W2^T ----
#pragma unroll 4
    for (int ks = 0; ks < 16; ++ks) {
        const int k0 = ks * 8;
        unsigned a[2][4];
#pragma unroll
        for (int mt = 0; mt < 2; ++mt) {
            const float* p = Abuf + (rw + 16 * mt + lr) * SA + k0 + lc;
            a[mt][0] = __float_as_uint(p[0]);
            a[mt][1] = __float_as_uint(p[8 * SA]);
            a[mt][2] = __float_as_uint(p[4]);
            a[mt][3] = __float_as_uint(p[8 * SA + 4]);
        }
        unsigned b[8][2];
#pragma unroll
        for (int nt = 0; nt < 8; ++nt) {
            const float* p = W2t + (k0 + lc) * SB + cw + 8 * nt + lr;
            b[nt][0] = __float_as_uint(p[0]);
            b[nt][1] = __float_as_uint(p[4 * SB]);
        }
#pragma unroll
        for (int mt = 0; mt < 2; ++mt)
#pragma unroll
            for (int nt = 0; nt < 8; ++nt) mma_tf32(acc[mt][nt], a[mt], b[nt]);
    }

    // Epilogue 2: bias + relu -> global.
#pragma unroll
    for (int mt = 0; mt < 2; ++mt) {
#pragma unroll
        for (int nt = 0; nt < 8; ++nt) {
            int col = cw + 8 * nt + 2 * lc;
            int r_a = rw + 16 * mt + lr;
            float bc0 = b2[col], bc1 = b2[col + 1];
            int row = row0 + r_a;
            if (row < n) {
                float2 v;
                v.x = fmaxf(acc[mt][nt][0] + bc0, 0.f);
                v.y = fmaxf(acc[mt][nt][1] + bc1, 0.f);
                *(float2*)(out + (long)row * D + col) = v;
            }
            if (row + 8 < n) {
                float2 v;
                v.x = fmaxf(acc[mt][nt][2] + bc0, 0.f);
                v.y = fmaxf(acc[mt][nt][3] + bc1, 0.f);
                *(float2*)(out + (long)(row + 8) * D + col) = v;
            }
        }
    }
}

// ---------------------------------------------------------------------------
extern "C" void kernel_launch(void* const* d_in, const int* in_sizes, int n_in,
                              void* d_out, int out_size) {
    const float* x  = (const float*)d_in[0];
    const int*   ei = (const int*)d_in[1];
    const float* W1 = (const float*)d_in[2];
    const float* b1 = (const float*)d_in[3];
    const float* W2 = (const float*)d_in[4];
    const float* b2 = (const float*)d_in[5];
    float* out = (float*)d_out;

    const int n = in_sizes[0] / D;
    const int E = in_sizes[1] / 2;
    const int* src = ei;
    const int* dst = ei + E;

    // K1: agg = 0
    {
        int total4 = n * (D / 4);
        int blocks = (total4 + 255) / 256;
        zero_agg_kernel<<<blocks, 256>>>(total4);
    }

    // K2: scatter-add
    {
        long threads = (long)E * 32;
        int blocks = (int)((threads + 255) / 256);
        scatter_kernel<<<blocks, 256>>>(x, src, dst, E);
    }

    // K3: fused tf32 MLP
    {
        int smem = (128 * SA + 2 * 128 * SB) * (int)sizeof(float);  // 206848 B
        cudaFuncSetAttribute(mlp_kernel,
                             cudaFuncAttributeMaxDynamicSharedMemorySize, smem);
        int blocks = (n + 127) / 128;
        mlp_kernel<<<blocks, 256, smem>>>(x, W1, b1, W2, b2, out, n);
    }
}

// round 9
// speedup vs baseline: 1.9350x; 1.2901x over previous
#include <cuda_runtime.h>
#include <cuda_bf16.h>

// ---------------------------------------------------------------------------
// GIN layer: out = relu( relu( (x + scatter_sum(x[src] -> dst)) @ W1^T + b1 ) @ W2^T + b2 )
// N = 100000, D = 128, E = 625000.
//
// R9: R4-style persistent MLP + reg prefetch, WITH the self-term restored
//     (R4..R7 all computed MLP(agg) instead of MLP(x+agg) -- that was the
//      sole bug behind the identical 0.3534 failures).
//   K1: agg = 0                   (vectorized zero kernel)
//   K2: agg[dst] += x[src]        (2 edges/warp, red.global.add.v4.f32)
//   K3: persistent fused tf32-MMA MLP; A = x + agg prefetched into registers
// ---------------------------------------------------------------------------

#define D 128
#define MAX_N 100000
#define SA 132
#define SB 136

__device__ float g_agg[(size_t)MAX_N * D];

// ---------------------------------------------------------------------------
__global__ void zero_agg_kernel(int total4) {
    int i = blockIdx.x * blockDim.x + threadIdx.x;
    if (i < total4) ((float4*)g_agg)[i] = make_float4(0.f, 0.f, 0.f, 0.f);
}

// ---------------------------------------------------------------------------
// Two edges per warp: lanes 0-15 -> edge 2w, lanes 16-31 -> edge 2w+1.
__global__ void scatter_kernel(const float* __restrict__ x,
                               const int* __restrict__ src,
                               const int* __restrict__ dst,
                               int E) {
    long tid  = (long)blockIdx.x * blockDim.x + threadIdx.x;
    int  wid  = (int)(tid >> 5);
    int  lane = (int)(tid & 31);
    int  e    = wid * 2 + (lane >> 4);
    int  l16  = lane & 15;
    if (e >= E) return;
    int s = src[e];
    int d = dst[e];
    const float* xs = x + (long)s * D + l16 * 8;
    float*       ad = g_agg + (long)d * D + l16 * 8;
    float4 v0 = *(const float4*)(xs);
    float4 v1 = *(const float4*)(xs + 4);
    asm volatile("red.global.add.v4.f32 [%0], {%1, %2, %3, %4};"
                 :: "l"(ad), "f"(v0.x), "f"(v0.y), "f"(v0.z), "f"(v0.w)
                 : "memory");
    asm volatile("red.global.add.v4.f32 [%0], {%1, %2, %3, %4};"
                 :: "l"(ad + 4), "f"(v1.x), "f"(v1.y), "f"(v1.z), "f"(v1.w)
                 : "memory");
}

// ---------------------------------------------------------------------------
__device__ __forceinline__ unsigned f2tf32(float f) {
    unsigned r;
    asm("cvt.rna.tf32.f32 %0, %1;" : "=r"(r) : "f"(f));
    return r;
}

__device__ __forceinline__ void mma_tf32(float c[4], const unsigned a[4],
                                         const unsigned b[2]) {
    asm volatile(
        "mma.sync.aligned.m16n8k8.row.col.f32.tf32.tf32.f32 "
        "{%0,%1,%2,%3}, {%4,%5,%6,%7}, {%8,%9}, {%0,%1,%2,%3};"
        : "+f"(c[0]), "+f"(c[1]), "+f"(c[2]), "+f"(c[3])
        : "r"(a[0]), "r"(a[1]), "r"(a[2]), "r"(a[3]), "r"(b[0]), "r"(b[1]));
}

// ---------------------------------------------------------------------------
// Persistent fused MLP. Grid = 148 CTAs x 256 threads; tiles strided by grid.
// Weights staged (tf32) once per CTA. Next tile (x+agg) prefetched into
// registers while the current tile's two GEMMs run.
__global__ __launch_bounds__(256, 1)
void mlp_kernel(const float* __restrict__ x,
                const float* __restrict__ W1, const float* __restrict__ b1,
                const float* __restrict__ W2, const float* __restrict__ b2,
                float* __restrict__ out, int n, int numTiles) {
    extern __shared__ float sm[];
    float* Abuf = sm;                     // 128*SA
    float* W1t  = sm + 128 * SA;          // 128*SB
    float* W2t  = W1t + 128 * SB;         // 128*SB

    const int tid  = threadIdx.x;
    const int w    = tid >> 5;
    const int lane = tid & 31;
    const int lr   = lane >> 2;
    const int lc   = lane & 3;
    const int rw   = (w & 3) * 32;
    const int cw   = (w >> 2) * 64;
    const int i0   = tid >> 5;   // row group for A staging
    const int k4   = tid & 31;   // float4 column chunk

    // Stage both weight matrices transposed (tf32) -- once per CTA.
    for (int idx = tid; idx < D * D; idx += 256) {
        int nn = idx >> 7;
        int m  = idx & 127;
        W1t[m * SB + nn] = __uint_as_float(f2tf32(W1[idx]));
        W2t[m * SB + nn] = __uint_as_float(f2tf32(W2[idx]));
    }

    // Prefetch first tile (A = x + agg) into registers.
    float4 r[16];
    int t = blockIdx.x;
    {
        int base = t * 128;
#pragma unroll
        for (int q = 0; q < 16; ++q) {
            int row = base + i0 + 8 * q;
            float4 v = make_float4(0.f, 0.f, 0.f, 0.f);
            if (row < n) {
                float4 vx = *(const float4*)(x + (long)row * D + k4 * 4);
                float4 vg = *(const float4*)(g_agg + (long)row * D + k4 * 4);
                v.x = vx.x + vg.x; v.y = vx.y + vg.y;
                v.z = vx.z + vg.z; v.w = vx.w + vg.w;
            }
            r[q] = v;
        }
    }

    for (; t < numTiles; t += gridDim.x) {
        const int row0 = t * 128;

        __syncthreads();   // prev iter's GEMM2 reads of Abuf complete; W visible (iter 0)

        // Store prefetched tile (tf32) into Abuf.
#pragma unroll
        for (int q = 0; q < 16; ++q) {
            uint4 u;
            u.x = f2tf32(r[q].x); u.y = f2tf32(r[q].y);
            u.z = f2tf32(r[q].z); u.w = f2tf32(r[q].w);
            *(uint4*)(Abuf + (i0 + 8 * q) * SA + k4 * 4) = u;
        }
        __syncthreads();

        // Prefetch next tile (A = x + agg) -- overlaps both GEMMs below.
        int tn = t + gridDim.x;
        if (tn < numTiles) {
            int base = tn * 128;
#pragma unroll
            for (int q = 0; q < 16; ++q) {
                int row = base + i0 + 8 * q;
                float4 v = make_float4(0.f, 0.f, 0.f, 0.f);
                if (row < n) {
                    float4 vx = *(const float4*)(x + (long)row * D + k4 * 4);
                    float4 vg = *(const float4*)(g_agg + (long)row * D + k4 * 4);
                    v.x = vx.x + vg.x; v.y = vx.y + vg.y;
                    v.z = vx.z + vg.z; v.w = vx.w + vg.w;
                }
                r[q] = v;
            }
        }

        float acc[2][8][4];
#pragma unroll
        for (int mt = 0; mt < 2; ++mt)
#pragma unroll
            for (int nt = 0; nt < 8; ++nt)
#pragma unroll
                for (int q = 0; q < 4; ++q) acc[mt][nt][q] = 0.f;

        // ---- GEMM 1: acc = A @ W1^T ----
#pragma unroll 4
        for (int ks = 0; ks < 16; ++ks) {
            const int k0 = ks * 8;
            unsigned a[2][4];
#pragma unroll
            for (int mt = 0; mt < 2; ++mt) {
                const float* p = Abuf + (rw + 16 * mt + lr) * SA + k0 + lc;
                a[mt][0] = __float_as_uint(p[0]);
                a[mt][1] = __float_as_uint(p[8 * SA]);
                a[mt][2] = __float_as_uint(p[4]);
                a[mt][3] = __float_as_uint(p[8 * SA + 4]);
            }
            unsigned b[8][2];
#pragma unroll
            for (int nt = 0; nt < 8; ++nt) {
                const float* p = W1t + (k0 + lc) * SB + cw + 8 * nt + lr;
                b[nt][0] = __float_as_uint(p[0]);
                b[nt][1] = __float_as_uint(p[4 * SB]);
            }
#pragma unroll
            for (int mt = 0; mt < 2; ++mt)
#pragma unroll
                for (int nt = 0; nt < 8; ++nt) mma_tf32(acc[mt][nt], a[mt], b[nt]);
        }
        __syncthreads();   // all warps done reading Abuf

        // Epilogue 1: bias + relu -> h1 (tf32) back into Abuf.
#pragma unroll
        for (int mt = 0; mt < 2; ++mt) {
#pragma unroll
            for (int nt = 0; nt < 8; ++nt) {
                int col = cw + 8 * nt + 2 * lc;
                int r_a = rw + 16 * mt + lr;
                float bc0 = b1[col], bc1 = b1[col + 1];
                uint2 u0, u1;
                u0.x = f2tf32(fmaxf(acc[mt][nt][0] + bc0, 0.f));
                u0.y = f2tf32(fmaxf(acc[mt][nt][1] + bc1, 0.f));
                u1.x = f2tf32(fmaxf(acc[mt][nt][2] + bc0, 0.f));
                u1.y = f2tf32(fmaxf(acc[mt][nt][3] + bc1, 0.f));
                *(uint2*)(Abuf + r_a * SA + col)       = u0;
                *(uint2*)(Abuf + (r_a + 8) * SA + col) = u1;
                acc[mt][nt][0] = acc[mt][nt][1] = 0.f;
                acc[mt][nt][2] = acc[mt][nt][3] = 0.f;
            }
        }
        __syncthreads();

        // ---- GEMM 2: acc = h1 @ W2^T ----
#pragma unroll 4
        for (int ks = 0; ks < 16; ++ks) {
            const int k0 = ks * 8;
            unsigned a[2][4];
#pragma unroll
            for (int mt = 0; mt < 2; ++mt) {
                const float* p = Abuf + (rw + 16 * mt + lr) * SA + k0 + lc;
                a[mt][0] = __float_as_uint(p[0]);
                a[mt][1] = __float_as_uint(p[8 * SA]);
                a[mt][2] = __float_as_uint(p[4]);
                a[mt][3] = __float_as_uint(p[8 * SA + 4]);
            }
            unsigned b[8][2];
#pragma unroll
            for (int nt = 0; nt < 8; ++nt) {
                const float* p = W2t + (k0 + lc) * SB + cw + 8 * nt + lr;
                b[nt][0] = __float_as_uint(p[0]);
                b[nt][1] = __float_as_uint(p[4 * SB]);
            }
#pragma unroll
            for (int mt = 0; mt < 2; ++mt)
#pragma unroll
                for (int nt = 0; nt < 8; ++nt) mma_tf32(acc[mt][nt], a[mt], b[nt]);
        }

        // Epilogue 2: bias + relu -> global.
#pragma unroll
        for (int mt = 0; mt < 2; ++mt) {
#pragma unroll
            for (int nt = 0; nt < 8; ++nt) {
                int col = cw + 8 * nt + 2 * lc;
                int r_a = rw + 16 * mt + lr;
                float bc0 = b2[col], bc1 = b2[col + 1];
                int row = row0 + r_a;
                if (row < n) {
                    float2 v;
                    v.x = fmaxf(acc[mt][nt][0] + bc0, 0.f);
                    v.y = fmaxf(acc[mt][nt][1] + bc1, 0.f);
                    *(float2*)(out + (long)row * D + col) = v;
                }
                if (row + 8 < n) {
                    float2 v;
                    v.x = fmaxf(acc[mt][nt][2] + bc0, 0.f);
                    v.y = fmaxf(acc[mt][nt][3] + bc1, 0.f);
                    *(float2*)(out + (long)(row + 8) * D + col) = v;
                }
            }
        }
    }
}

// ---------------------------------------------------------------------------
extern "C" void kernel_launch(void* const* d_in, const int* in_sizes, int n_in,
                              void* d_out, int out_size) {
    const float* x  = (const float*)d_in[0];
    const int*   ei = (const int*)d_in[1];
    const float* W1 = (const float*)d_in[2];
    const float* b1 = (const float*)d_in[3];
    const float* W2 = (const float*)d_in[4];
    const float* b2 = (const float*)d_in[5];
    float* out = (float*)d_out;

    const int n = in_sizes[0] / D;
    const int E = in_sizes[1] / 2;
    const int* src = ei;
    const int* dst = ei + E;

    // K1: agg = 0
    {
        int total4 = n * (D / 4);
        int blocks = (total4 + 255) / 256;
        zero_agg_kernel<<<blocks, 256>>>(total4);
    }

    // K2: scatter-add (2 edges per warp)
    {
        long warps   = ((long)E + 1) / 2;
        long threads = warps * 32;
        int  blocks  = (int)((threads + 255) / 256);
        scatter_kernel<<<blocks, 256>>>(x, src, dst, E);
    }

    // K3: persistent fused tf32 MLP (A = x + agg)
    {
        int smem = (128 * SA + 2 * 128 * SB) * (int)sizeof(float);  // 206848 B
        cudaFuncSetAttribute(mlp_kernel,
                             cudaFuncAttributeMaxDynamicSharedMemorySize, smem);
        int numTiles = (n + 127) / 128;
        mlp_kernel<<<148, 256, smem>>>(x, W1, b1, W2, b2, out, n, numTiles);
    }
}

// round 11
// speedup vs baseline: 2.1715x; 1.1222x over previous
#include <cuda_runtime.h>
#include <cuda_bf16.h>

// ---------------------------------------------------------------------------
// GIN layer: out = relu( relu( (x + scatter_sum(x[src] -> dst)) @ W1^T + b1 ) @ W2^T + b2 )
// N = 100000, D = 128, E = 625000.
//
// R11: bulk-reduce scatter, ONE-SHOT form (no persistent loop / double buffer
//      -> structurally hang-free). One block = 32 edges; stage rows in smem;
//      lanes 0-31 issue one cp.reduce.async.bulk.add.f32 (512 B) each.
//      MLP = R9 proven persistent tf32-MMA kernel (A = x + agg, reg prefetch).
// ---------------------------------------------------------------------------

#define D 128
#define MAX_N 100000
#define SA 132
#define SB 136
#define EPB 32           // edges per block in the scatter

__device__ float g_agg[(size_t)MAX_N * D];

// ---------------------------------------------------------------------------
__global__ void zero_agg_kernel(int total4) {
    int i = blockIdx.x * blockDim.x + threadIdx.x;
    if (i < total4) ((float4*)g_agg)[i] = make_float4(0.f, 0.f, 0.f, 0.f);
}

// ---------------------------------------------------------------------------
__device__ __forceinline__ unsigned smem_u32(const void* p) {
    unsigned a;
    asm("{ .reg .u64 t; cvta.to.shared.u64 t, %1; cvt.u32.u64 %0, t; }"
        : "=r"(a) : "l"(p));
    return a;
}

// One-shot bulk-reduce scatter. Block = 128 threads, EPB=32 edges.
__global__ __launch_bounds__(128, 8)
void scatter_bulk_kernel(const float* __restrict__ x,
                         const int* __restrict__ src,
                         const int* __restrict__ dst,
                         int E) {
    __shared__ __align__(16) float buf[EPB][D];   // 16 KB

    const int tid = threadIdx.x;
    const int e0  = blockIdx.x * EPB;

    // Stage: thread layout (r4 = tid>>2 covers 32 rows, c4 = tid&3), each
    // thread loads 8 float4 spread across its row (32 float4 per row).
    {
        const int r  = tid >> 2;          // 0..31: row
        const int c0 = tid & 3;           // 0..3
        int e = e0 + r;
        if (e < E) {
            const float4* xs = (const float4*)(x + (long)src[e] * D);
            float4* bb = (float4*)&buf[r][0];
#pragma unroll
            for (int q = 0; q < 8; ++q) {
                bb[c0 + q * 4] = xs[c0 + q * 4];
            }
        }
    }
    __syncthreads();
    asm volatile("fence.proxy.async.shared::cta;" ::: "memory");

    // Lanes 0..31 (warp 0) each issue one 512 B bulk reduce.
    if (tid < EPB) {
        int e = e0 + tid;
        if (e < E) {
            unsigned saddr = smem_u32(&buf[tid][0]);
            float* g = g_agg + (long)dst[e] * D;
            asm volatile(
                "cp.reduce.async.bulk.global.shared::cta.bulk_group.add.f32 "
                "[%0], [%1], 512;"
                :: "l"(g), "r"(saddr) : "memory");
        }
        asm volatile("cp.async.bulk.commit_group;" ::: "memory");
        asm volatile("cp.async.bulk.wait_group 0;" ::: "memory");
    }
}

// ---------------------------------------------------------------------------
__device__ __forceinline__ unsigned f2tf32(float f) {
    unsigned r;
    asm("cvt.rna.tf32.f32 %0, %1;" : "=r"(r) : "f"(f));
    return r;
}

__device__ __forceinline__ void mma_tf32(float c[4], const unsigned a[4],
                                         const unsigned b[2]) {
    asm volatile(
        "mma.sync.aligned.m16n8k8.row.col.f32.tf32.tf32.f32 "
        "{%0,%1,%2,%3}, {%4,%5,%6,%7}, {%8,%9}, {%0,%1,%2,%3};"
        : "+f"(c[0]), "+f"(c[1]), "+f"(c[2]), "+f"(c[3])
        : "r"(a[0]), "r"(a[1]), "r"(a[2]), "r"(a[3]), "r"(b[0]), "r"(b[1]));
}

// ---------------------------------------------------------------------------
// Persistent fused MLP (R9 proven). Grid = 148 CTAs x 256 threads.
__global__ __launch_bounds__(256, 1)
void mlp_kernel(const float* __restrict__ x,
                const float* __restrict__ W1, const float* __restrict__ b1,
                const float* __restrict__ W2, const float* __restrict__ b2,
                float* __restrict__ out, int n, int numTiles) {
    extern __shared__ float sm[];
    float* Abuf = sm;                     // 128*SA
    float* W1t  = sm + 128 * SA;          // 128*SB
    float* W2t  = W1t + 128 * SB;         // 128*SB

    const int tid  = threadIdx.x;
    const int w    = tid >> 5;
    const int lane = tid & 31;
    const int lr   = lane >> 2;
    const int lc   = lane & 3;
    const int rw   = (w & 3) * 32;
    const int cw   = (w >> 2) * 64;
    const int i0   = tid >> 5;
    const int k4   = tid & 31;

    for (int idx = tid; idx < D * D; idx += 256) {
        int nn = idx >> 7;
        int m  = idx & 127;
        W1t[m * SB + nn] = __uint_as_float(f2tf32(W1[idx]));
        W2t[m * SB + nn] = __uint_as_float(f2tf32(W2[idx]));
    }

    float4 r[16];
    int t = blockIdx.x;
    {
        int base = t * 128;
#pragma unroll
        for (int q = 0; q < 16; ++q) {
            int row = base + i0 + 8 * q;
            float4 v = make_float4(0.f, 0.f, 0.f, 0.f);
            if (row < n) {
                float4 vx = *(const float4*)(x + (long)row * D + k4 * 4);
                float4 vg = *(const float4*)(g_agg + (long)row * D + k4 * 4);
                v.x = vx.x + vg.x; v.y = vx.y + vg.y;
                v.z = vx.z + vg.z; v.w = vx.w + vg.w;
            }
            r[q] = v;
        }
    }

    for (; t < numTiles; t += gridDim.x) {
        const int row0 = t * 128;

        __syncthreads();

#pragma unroll
        for (int q = 0; q < 16; ++q) {
            uint4 u;
            u.x = f2tf32(r[q].x); u.y = f2tf32(r[q].y);
            u.z = f2tf32(r[q].z); u.w = f2tf32(r[q].w);
            *(uint4*)(Abuf + (i0 + 8 * q) * SA + k4 * 4) = u;
        }
        __syncthreads();

        int tn = t + gridDim.x;
        if (tn < numTiles) {
            int base = tn * 128;
#pragma unroll
            for (int q = 0; q < 16; ++q) {
                int row = base + i0 + 8 * q;
                float4 v = make_float4(0.f, 0.f, 0.f, 0.f);
                if (row < n) {
                    float4 vx = *(const float4*)(x + (long)row * D + k4 * 4);
                    float4 vg = *(const float4*)(g_agg + (long)row * D + k4 * 4);
                    v.x = vx.x + vg.x; v.y = vx.y + vg.y;
                    v.z = vx.z + vg.z; v.w = vx.w + vg.w;
                }
                r[q] = v;
            }
        }

        float acc[2][8][4];
#pragma unroll
        for (int mt = 0; mt < 2; ++mt)
#pragma unroll
            for (int nt = 0; nt < 8; ++nt)
#pragma unroll
                for (int q = 0; q < 4; ++q) acc[mt][nt][q] = 0.f;

        // ---- GEMM 1 ----
#pragma unroll 4
        for (int ks = 0; ks < 16; ++ks) {
            const int k0 = ks * 8;
            unsigned a[2][4];
#pragma unroll
            for (int mt = 0; mt < 2; ++mt) {
                const float* p = Abuf + (rw + 16 * mt + lr) * SA + k0 + lc;
                a[mt][0] = __float_as_uint(p[0]);
                a[mt][1] = __float_as_uint(p[8 * SA]);
                a[mt][2] = __float_as_uint(p[4]);
                a[mt][3] = __float_as_uint(p[8 * SA + 4]);
            }
            unsigned b[8][2];
#pragma unroll
            for (int nt = 0; nt < 8; ++nt) {
                const float* p = W1t + (k0 + lc) * SB + cw + 8 * nt + lr;
                b[nt][0] = __float_as_uint(p[0]);
                b[nt][1] = __float_as_uint(p[4 * SB]);
            }
#pragma unroll
            for (int mt = 0; mt < 2; ++mt)
#pragma unroll
                for (int nt = 0; nt < 8; ++nt) mma_tf32(acc[mt][nt], a[mt], b[nt]);
        }
        __syncthreads();

        // Epilogue 1: bias + relu -> h1 (tf32) in Abuf.
#pragma unroll
        for (int mt = 0; mt < 2; ++mt) {
#pragma unroll
            for (int nt = 0; nt < 8; ++nt) {
                int col = cw + 8 * nt + 2 * lc;
                int r_a = rw + 16 * mt + lr;
                float bc0 = b1[col], bc1 = b1[col + 1];
                uint2 u0, u1;
                u0.x = f2tf32(fmaxf(acc[mt][nt][0] + bc0, 0.f));
                u0.y = f2tf32(fmaxf(acc[mt][nt][1] + bc1, 0.f));
                u1.x = f2tf32(fmaxf(acc[mt][nt][2] + bc0, 0.f));
                u1.y = f2tf32(fmaxf(acc[mt][nt][3] + bc1, 0.f));
                *(uint2*)(Abuf + r_a * SA + col)       = u0;
                *(uint2*)(Abuf + (r_a + 8) * SA + col) = u1;
                acc[mt][nt][0] = acc[mt][nt][1] = 0.f;
                acc[mt][nt][2] = acc[mt][nt][3] = 0.f;
            }
        }
        __syncthreads();

        // ---- GEMM 2 ----
#pragma unroll 4
        for (int ks = 0; ks < 16; ++ks) {
            const int k0 = ks * 8;
            unsigned a[2][4];
#pragma unroll
            for (int mt = 0; mt < 2; ++mt) {
                const float* p = Abuf + (rw + 16 * mt + lr) * SA + k0 + lc;
                a[mt][0] = __float_as_uint(p[0]);
                a[mt][1] = __float_as_uint(p[8 * SA]);
                a[mt][2] = __float_as_uint(p[4]);
                a[mt][3] = __float_as_uint(p[8 * SA + 4]);
            }
            unsigned b[8][2];
#pragma unroll
            for (int nt = 0; nt < 8; ++nt) {
                const float* p = W2t + (k0 + lc) * SB + cw + 8 * nt + lr;
                b[nt][0] = __float_as_uint(p[0]);
                b[nt][1] = __float_as_uint(p[4 * SB]);
            }
#pragma unroll
            for (int mt = 0; mt < 2; ++mt)
#pragma unroll
                for (int nt = 0; nt < 8; ++nt) mma_tf32(acc[mt][nt], a[mt], b[nt]);
        }

        // Epilogue 2: bias + relu -> global.
#pragma unroll
        for (int mt = 0; mt < 2; ++mt) {
#pragma unroll
            for (int nt = 0; nt < 8; ++nt) {
                int col = cw + 8 * nt + 2 * lc;
                int r_a = rw + 16 * mt + lr;
                float bc0 = b2[col], bc1 = b2[col + 1];
                int row = row0 + r_a;
                if (row < n) {
                    float2 v;
                    v.x = fmaxf(acc[mt][nt][0] + bc0, 0.f);
                    v.y = fmaxf(acc[mt][nt][1] + bc1, 0.f);
                    *(float2*)(out + (long)row * D + col) = v;
                }
                if (row + 8 < n) {
                    float2 v;
                    v.x = fmaxf(acc[mt][nt][2] + bc0, 0.f);
                    v.y = fmaxf(acc[mt][nt][3] + bc1, 0.f);
                    *(float2*)(out + (long)(row + 8) * D + col) = v;
                }
            }
        }
    }
}

// ---------------------------------------------------------------------------
extern "C" void kernel_launch(void* const* d_in, const int* in_sizes, int n_in,
                              void* d_out, int out_size) {
    const float* x  = (const float*)d_in[0];
    const int*   ei = (const int*)d_in[1];
    const float* W1 = (const float*)d_in[2];
    const float* b1 = (const float*)d_in[3];
    const float* W2 = (const float*)d_in[4];
    const float* b2 = (const float*)d_in[5];
    float* out = (float*)d_out;

    const int n = in_sizes[0] / D;
    const int E = in_sizes[1] / 2;
    const int* src = ei;
    const int* dst = ei + E;

    // K1: agg = 0
    {
        int total4 = n * (D / 4);
        int blocks = (total4 + 255) / 256;
        zero_agg_kernel<<<blocks, 256>>>(total4);
    }

    // K2: bulk-reduce scatter (one-shot blocks)
    {
        int blocks = (E + EPB - 1) / EPB;
        scatter_bulk_kernel<<<blocks, 128>>>(x, src, dst, E);
    }

    // K3: persistent fused tf32 MLP (A = x + agg)
    {
        int smem = (128 * SA + 2 * 128 * SB) * (int)sizeof(float);  // 206848 B
        cudaFuncSetAttribute(mlp_kernel,
                             cudaFuncAttributeMaxDynamicSharedMemorySize, smem);
        int numTiles = (n + 127) / 128;
        mlp_kernel<<<148, 256, smem>>>(x, W1, b1, W2, b2, out, n, numTiles);
    }
}